// round 3
// baseline (speedup 1.0000x reference)
#include <cuda_runtime.h>
#include <math.h>

#define BB 128
#define SS 256
#define HH 512

// ---------------- device scratch (no allocations allowed) -------------------
__device__ float g_rsWr[HH];            // rowsum(Wr)
__device__ float g_rsW[HH];             // rowsum(W)
__device__ float g_part[8][BB * SS];    // per-jblock logit partials
__device__ float g_Gt[SS * BB];         // softmax gates, (s, b)
__device__ float g_C[2][HH * BB];       // recurrent state, transposed (h, b)

// ---------------- prep: rowsums of Wr and W ---------------------------------
// pre_r[b,s,h] = facts*rowsum(Wr)[h] + br[h]; same for W. One warp per row.
__global__ void prep_kernel(const float* __restrict__ Wr, const float* __restrict__ W)
{
    int warp = threadIdx.x >> 5, lane = threadIdx.x & 31;
    int rowId = blockIdx.x * 8 + warp;               // 0..1023
    const float* src = (rowId < HH) ? Wr : W;
    int h = rowId & (HH - 1);
    const float4* s4 = reinterpret_cast<const float4*>(src + (size_t)h * HH);
    float s = 0.f;
    for (int i = lane; i < HH / 4; i += 32) {
        float4 v = s4[i];
        s += (v.x + v.y) + (v.z + v.w);
    }
#pragma unroll
    for (int o = 16; o > 0; o >>= 1) s += __shfl_xor_sync(0xffffffffu, s, o);
    if (lane == 0) {
        if (rowId < HH) g_rsWr[h] = s;
        else            g_rsW[h]  = s;
    }
}

// ---------------- gate MLP: fused z-build + GEMM + tanh + z2 dot ------------
// grid (S/128, H/64, B), 256 threads. 128x64 tile, K=2048 built on the fly.
__global__ void __launch_bounds__(256) gate_kernel(
    const float* __restrict__ facts, const float* __restrict__ q,
    const float* __restrict__ m, const float* __restrict__ z1w,
    const float* __restrict__ z1b, const float* __restrict__ z2w)
{
    __shared__ float qs[HH], ms[HH];
    __shared__ float As[4][16][128];   // 4 z-variants of the facts k-tile
    __shared__ float Bs[16][64];

    int tid = threadIdx.x;
    int b  = blockIdx.z;
    int s0 = blockIdx.x * 128;
    int j0 = blockIdx.y * 64;

    for (int i = tid; i < HH; i += 256) {
        qs[i] = q[b * HH + i];
        ms[i] = m[b * HH + i];
    }

    int tx = tid & 15, ty = tid >> 4;
    float acc[8][4];
#pragma unroll
    for (int i = 0; i < 8; i++)
#pragma unroll
        for (int j = 0; j < 4; j++) acc[i][j] = 0.f;

    const float* fb = facts + ((size_t)b * SS + s0) * HH;

    for (int k0 = 0; k0 < HH; k0 += 16) {
        __syncthreads();   // prev compute done (also covers qs/ms on k0==0)
        // build all 4 z-variants for this facts k-tile
        for (int i = tid; i < 128 * 16; i += 256) {
            int ss = i >> 4, kk = i & 15;
            float fv = fb[(size_t)ss * HH + k0 + kk];
            float qv = qs[k0 + kk], mv = ms[k0 + kk];
            As[0][kk][ss] = fv * qv;
            As[1][kk][ss] = fv * mv;
            As[2][kk][ss] = fabsf(fv - qv);
            As[3][kk][ss] = fabsf(fv - mv);
        }
        for (int blk = 0; blk < 4; blk++) {
            __syncthreads();   // As ready / prev Bs consumed
            {
                int kk = tid >> 6, jj = tid & 63;
                int rowbase = blk * HH + k0 + kk;
#pragma unroll
                for (int r = 0; r < 4; r++)
                    Bs[kk + r * 4][jj] = z1w[(size_t)(rowbase + r * 4) * HH + j0 + jj];
            }
            __syncthreads();   // Bs ready
#pragma unroll
            for (int kk = 0; kk < 16; kk++) {
                float4 a0 = *reinterpret_cast<const float4*>(&As[blk][kk][ty * 8]);
                float4 a1 = *reinterpret_cast<const float4*>(&As[blk][kk][ty * 8 + 4]);
                float4 bv = *reinterpret_cast<const float4*>(&Bs[kk][tx * 4]);
                float av[8] = {a0.x, a0.y, a0.z, a0.w, a1.x, a1.y, a1.z, a1.w};
                float bw4[4] = {bv.x, bv.y, bv.z, bv.w};
#pragma unroll
                for (int i = 0; i < 8; i++)
#pragma unroll
                    for (int j = 0; j < 4; j++)
                        acc[i][j] = fmaf(av[i], bw4[j], acc[i][j]);
            }
        }
    }

    // epilogue: tanh, dot with z2_w, reduce over the 64 j's of this block
    float z1bv[4], z2wv[4];
#pragma unroll
    for (int j = 0; j < 4; j++) {
        int jc = j0 + tx * 4 + j;
        z1bv[j] = z1b[jc];
        z2wv[j] = z2w[jc];
    }
    float p[8];
#pragma unroll
    for (int i = 0; i < 8; i++) {
        float s = 0.f;
#pragma unroll
        for (int j = 0; j < 4; j++) {
            float t = tanhf(acc[i][j] + z1bv[j]);
            s = fmaf(t, z2wv[j], s);
        }
        p[i] = s;
    }
    // reduce across tx (16 lanes within each half-warp)
#pragma unroll
    for (int i = 0; i < 8; i++) {
#pragma unroll
        for (int o = 8; o > 0; o >>= 1)
            p[i] += __shfl_xor_sync(0xffffffffu, p[i], o);
    }
    if (tx == 0) {
#pragma unroll
        for (int i = 0; i < 8; i++)
            g_part[blockIdx.y][b * SS + s0 + ty * 8 + i] = p[i];
    }
}

// ---------------- softmax over S per batch -----------------------------------
__global__ void softmax_kernel()
{
    int b = blockIdx.x, s = threadIdx.x;   // 256 threads
    float l = 0.f;
#pragma unroll
    for (int jb = 0; jb < 8; jb++) l += g_part[jb][b * SS + s];
    __shared__ float sm[256];
    sm[s] = l;
    __syncthreads();
#pragma unroll
    for (int o = 128; o > 0; o >>= 1) {
        if (s < o) sm[s] = fmaxf(sm[s], sm[s + o]);
        __syncthreads();
    }
    float mx = sm[0];
    __syncthreads();
    float e = expf(l - mx);
    sm[s] = e;
    __syncthreads();
#pragma unroll
    for (int o = 128; o > 0; o >>= 1) {
        if (s < o) sm[s] += sm[s + o];
        __syncthreads();
    }
    g_Gt[s * BB + b] = e / sm[0];
}

// ---------------- zero initial C ---------------------------------------------
__global__ void zeroC_kernel()
{
    g_C[0][blockIdx.x * 256 + threadIdx.x] = 0.f;
}

// ---------------- one scan step: C' = g*tanh(...)+(1-g)*C --------------------
// grid 128 (4 h each), 256 threads = 4-way ksplit x (2h x 32 b-quads).
__global__ void __launch_bounds__(256) scan_kernel(
    const float* __restrict__ facts,
    const float* __restrict__ Ur, const float* __restrict__ U,
    const float* __restrict__ br, const float* __restrict__ bur,
    const float* __restrict__ bw, const float* __restrict__ bu,
    int s)
{
    const float* __restrict__ Cin = g_C[s & 1];
    float* __restrict__ Cout = g_C[(s + 1) & 1];
    int h0 = blockIdx.x * 4;

    __shared__ float Cs[32][128];      // C k-tile, (k, b)
    __shared__ float Uc[32][2][4];     // [kk][hp][{Ur(h),Ur(h+1),U(h),U(h+1)}]
    __shared__ float red[4][64][16];   // ksplit partials

    int tid = threadIdx.x;
    int kq   = tid >> 6;       // 0..3  ksplit
    int slot = tid & 63;
    int hp   = slot >> 5;      // 0..1  h-pair
    int bq   = slot & 31;      // b quad = bq*4

    float acc[16];
#pragma unroll
    for (int i = 0; i < 16; i++) acc[i] = 0.f;

    for (int kt = 0; kt < HH; kt += 32) {
        __syncthreads();
        for (int i = tid; i < 32 * 128; i += 256)
            Cs[i >> 7][i & 127] = Cin[(size_t)(kt + (i >> 7)) * BB + (i & 127)];
        {
            int kk = tid >> 3;          // 0..31
            int hpf = (tid >> 2) & 1;
            int e = tid & 3;
            int h = h0 + hpf * 2 + (e & 1);
            const float* src = (e < 2) ? Ur : U;
            Uc[kk][hpf][e] = src[(size_t)(kt + kk) * HH + h];
        }
        __syncthreads();
#pragma unroll
        for (int k8 = 0; k8 < 8; k8++) {
            int kk = kq * 8 + k8;
            float4 cv = *reinterpret_cast<const float4*>(&Cs[kk][bq * 4]);
            float4 uv = *reinterpret_cast<const float4*>(&Uc[kk][hp][0]);
            float c4[4] = {cv.x, cv.y, cv.z, cv.w};
#pragma unroll
            for (int bl = 0; bl < 4; bl++) {
                acc[bl * 2 + 0]     = fmaf(c4[bl], uv.x, acc[bl * 2 + 0]);     // h, Ur
                acc[bl * 2 + 1]     = fmaf(c4[bl], uv.z, acc[bl * 2 + 1]);     // h, U
                acc[8 + bl * 2 + 0] = fmaf(c4[bl], uv.y, acc[8 + bl * 2 + 0]); // h+1, Ur
                acc[8 + bl * 2 + 1] = fmaf(c4[bl], uv.w, acc[8 + bl * 2 + 1]); // h+1, U
            }
        }
    }
    __syncthreads();
#pragma unroll
    for (int i = 0; i < 16; i++) red[kq][slot][i] = acc[i];
    __syncthreads();

    // fused epilogue: each thread finalizes 2 (h, b) outputs
#pragma unroll
    for (int e = 0; e < 2; e++) {
        int p = tid * 2 + e;               // 0..511
        int h_l = p >> 7;                  // 0..3
        int b = p & 127;
        int php = h_l >> 1, hloc = h_l & 1;
        int pslot = php * 32 + (b >> 2);
        int iR = hloc * 8 + (b & 3) * 2;
        float accR = red[0][pslot][iR] + red[1][pslot][iR] +
                     red[2][pslot][iR] + red[3][pslot][iR];
        float accU = red[0][pslot][iR + 1] + red[1][pslot][iR + 1] +
                     red[2][pslot][iR + 1] + red[3][pslot][iR + 1];
        int h = h0 + h_l;
        float fv = facts[((size_t)b * SS + s) * HH + h];
        float prer = fmaf(fv, g_rsWr[h], br[h]);
        float preh = fmaf(fv, g_rsW[h], bw[h]);
        float r  = 1.f / (1.f + expf(-(prer + accR + bur[h])));
        float ht = tanhf(fmaf(r, accU + bu[h], preh));
        float g  = g_Gt[s * BB + b];
        float c  = Cin[(size_t)h * BB + b];
        Cout[(size_t)h * BB + b] = fmaf(g, ht - c, c);
    }
}

// ---------------- final: relu(concat @ nm_w + nm_b) --------------------------
__global__ void __launch_bounds__(512) final_kernel(
    const float* __restrict__ prevM, const float* __restrict__ q,
    const float* __restrict__ nm_w, const float* __restrict__ nm_b,
    float* __restrict__ out)
{
    __shared__ float cs[3 * HH];
    int b = blockIdx.x, tid = threadIdx.x;    // 512 threads
    cs[tid]          = prevM[b * HH + tid];
    cs[HH + tid]     = g_C[0][(size_t)tid * BB + b];   // final C lives in buffer 0
    cs[2 * HH + tid] = q[b * HH + tid];
    __syncthreads();
    float acc = nm_b[tid];
#pragma unroll 8
    for (int k = 0; k < 3 * HH; k++)
        acc = fmaf(cs[k], nm_w[(size_t)k * HH + tid], acc);
    out[b * HH + tid] = fmaxf(acc, 0.f);
}

// ---------------- launch ------------------------------------------------------
extern "C" void kernel_launch(void* const* d_in, const int* in_sizes, int n_in,
                              void* d_out, int out_size)
{
    const float* facts     = (const float*)d_in[0];
    const float* questions = (const float*)d_in[1];
    const float* prevM     = (const float*)d_in[2];
    const float* z1_w      = (const float*)d_in[3];
    const float* z1_b      = (const float*)d_in[4];
    const float* z2_w      = (const float*)d_in[5];
    // d_in[6] z2_b: constant shift, softmax-invariant — unused
    const float* Wr        = (const float*)d_in[7];
    const float* br        = (const float*)d_in[8];
    const float* Ur        = (const float*)d_in[9];
    const float* bur       = (const float*)d_in[10];
    const float* W         = (const float*)d_in[11];
    const float* bw        = (const float*)d_in[12];
    const float* U         = (const float*)d_in[13];
    const float* bu        = (const float*)d_in[14];
    const float* nm_w      = (const float*)d_in[15];
    const float* nm_b      = (const float*)d_in[16];
    float* out = (float*)d_out;

    prep_kernel<<<128, 256>>>(Wr, W);
    gate_kernel<<<dim3(2, 8, BB), 256>>>(facts, questions, prevM, z1_w, z1_b, z2_w);
    softmax_kernel<<<BB, 256>>>();
    zeroC_kernel<<<256, 256>>>();
    for (int s = 0; s < SS; s++)
        scan_kernel<<<128, 256>>>(facts, Ur, U, br, bur, bw, bu, s);
    final_kernel<<<BB, 512>>>(prevM, questions, nm_w, nm_b, out);
}

// round 4
// speedup vs baseline: 1.7386x; 1.7386x over previous
#include <cuda_runtime.h>
#include <math.h>

#define BB 128
#define SS 256
#define HH 512
#define NBLK 128

// ---------------- device scratch (no allocations allowed) -------------------
__device__ float g_rsWr[HH];            // rowsum(Wr)
__device__ float g_rsW[HH];             // rowsum(W)
__device__ float g_part[8][BB * SS];    // per-jblock logit partials
__device__ float g_Gt[SS * BB];         // softmax gates, (s, b)
__device__ float g_C[2][HH * BB];       // recurrent state, transposed (h, b)
__device__ unsigned g_cnt;              // grid barrier counter (stays 0 between runs)
__device__ unsigned g_gen;              // grid barrier generation

// ---------------- f32x2 helpers ----------------------------------------------
__device__ __forceinline__ unsigned long long pk2(float x, float y) {
    unsigned long long r;
    asm("mov.b64 %0, {%1,%2};" : "=l"(r) : "f"(x), "f"(y));
    return r;
}
__device__ __forceinline__ void upk2(unsigned long long v, float& x, float& y) {
    asm("mov.b64 {%0,%1}, %2;" : "=f"(x), "=f"(y) : "l"(v));
}
__device__ __forceinline__ unsigned long long fma2_(unsigned long long a,
                                                    unsigned long long b,
                                                    unsigned long long c) {
    unsigned long long d;
    asm("fma.rn.f32x2 %0, %1, %2, %3;" : "=l"(d) : "l"(a), "l"(b), "l"(c));
    return d;
}
__device__ __forceinline__ unsigned long long add2_(unsigned long long a,
                                                    unsigned long long b) {
    unsigned long long d;
    asm("add.rn.f32x2 %0, %1, %2;" : "=l"(d) : "l"(a), "l"(b));
    return d;
}

// ---------------- grid-wide barrier (all NBLK blocks co-resident) ------------
__device__ __forceinline__ void grid_sync() {
    __syncthreads();
    if (threadIdx.x == 0) {
        unsigned gen = atomicAdd(&g_gen, 0u);       // snapshot generation
        unsigned old = atomicAdd(&g_cnt, 1u);
        if (old == NBLK - 1) {
            g_cnt = 0;                               // safe: nobody polls g_cnt
            __threadfence();
            atomicAdd(&g_gen, 1u);
        } else {
            while (atomicAdd(&g_gen, 0u) == gen) {}
        }
        __threadfence();
    }
    __syncthreads();
}

// ---------------- prep: rowsums of Wr and W ----------------------------------
__global__ void prep_kernel(const float* __restrict__ Wr, const float* __restrict__ W)
{
    int warp = threadIdx.x >> 5, lane = threadIdx.x & 31;
    int rowId = blockIdx.x * 8 + warp;               // 0..1023
    const float* src = (rowId < HH) ? Wr : W;
    int h = rowId & (HH - 1);
    const float4* s4 = reinterpret_cast<const float4*>(src + (size_t)h * HH);
    float s = 0.f;
    for (int i = lane; i < HH / 4; i += 32) {
        float4 v = s4[i];
        s += (v.x + v.y) + (v.z + v.w);
    }
#pragma unroll
    for (int o = 16; o > 0; o >>= 1) s += __shfl_xor_sync(0xffffffffu, s, o);
    if (lane == 0) {
        if (rowId < HH) g_rsWr[h] = s;
        else            g_rsW[h]  = s;
    }
}

// ---------------- gate MLP: fused z-build + GEMM (f32x2) + tanh + z2 dot -----
// grid (S/128, H/64, B), 256 threads. 128x64 tile, K=2048 built on the fly.
__global__ void __launch_bounds__(256) gate_kernel(
    const float* __restrict__ facts, const float* __restrict__ q,
    const float* __restrict__ m, const float* __restrict__ z1w,
    const float* __restrict__ z1b, const float* __restrict__ z2w)
{
    __shared__ float qs[HH], ms[HH];
    __shared__ float As[4][16][128];   // 4 z-variants of the facts k-tile
    __shared__ float Bs[16][64];

    int tid = threadIdx.x;
    int b  = blockIdx.z;
    int s0 = blockIdx.x * 128;
    int j0 = blockIdx.y * 64;

    for (int i = tid; i < HH; i += 256) {
        qs[i] = q[b * HH + i];
        ms[i] = m[b * HH + i];
    }

    int tx = tid & 15, ty = tid >> 4;
    unsigned long long acc2[4][4];      // [s-pair][j]
#pragma unroll
    for (int i = 0; i < 4; i++)
#pragma unroll
        for (int j = 0; j < 4; j++) acc2[i][j] = 0ull;

    const float* fb = facts + ((size_t)b * SS + s0) * HH;

    for (int k0 = 0; k0 < HH; k0 += 16) {
        __syncthreads();   // prev compute done (also covers qs/ms on k0==0)
        for (int i = tid; i < 128 * 16; i += 256) {
            int ss = i >> 4, kk = i & 15;
            float fv = fb[(size_t)ss * HH + k0 + kk];
            float qv = qs[k0 + kk], mv = ms[k0 + kk];
            As[0][kk][ss] = fv * qv;
            As[1][kk][ss] = fv * mv;
            As[2][kk][ss] = fabsf(fv - qv);
            As[3][kk][ss] = fabsf(fv - mv);
        }
        for (int blk = 0; blk < 4; blk++) {
            __syncthreads();   // As ready / prev Bs consumed
            {
                int kk = tid >> 6, jj = tid & 63;
                int rowbase = blk * HH + k0 + kk;
#pragma unroll
                for (int r = 0; r < 4; r++)
                    Bs[kk + r * 4][jj] = z1w[(size_t)(rowbase + r * 4) * HH + j0 + jj];
            }
            __syncthreads();   // Bs ready
#pragma unroll
            for (int kk = 0; kk < 16; kk++) {
                float4 a0 = *reinterpret_cast<const float4*>(&As[blk][kk][ty * 8]);
                float4 a1 = *reinterpret_cast<const float4*>(&As[blk][kk][ty * 8 + 4]);
                float4 bv = *reinterpret_cast<const float4*>(&Bs[kk][tx * 4]);
                unsigned long long ap[4] = {pk2(a0.x, a0.y), pk2(a0.z, a0.w),
                                            pk2(a1.x, a1.y), pk2(a1.z, a1.w)};
                unsigned long long bd[4] = {pk2(bv.x, bv.x), pk2(bv.y, bv.y),
                                            pk2(bv.z, bv.z), pk2(bv.w, bv.w)};
#pragma unroll
                for (int i = 0; i < 4; i++)
#pragma unroll
                    for (int j = 0; j < 4; j++)
                        acc2[i][j] = fma2_(ap[i], bd[j], acc2[i][j]);
            }
        }
    }

    // epilogue: tanh, dot with z2_w, reduce over the 64 j's of this block
    float z1bv[4], z2wv[4];
#pragma unroll
    for (int j = 0; j < 4; j++) {
        int jc = j0 + tx * 4 + j;
        z1bv[j] = z1b[jc];
        z2wv[j] = z2w[jc];
    }
    float p[8];
#pragma unroll
    for (int i = 0; i < 8; i++) p[i] = 0.f;
#pragma unroll
    for (int ip = 0; ip < 4; ip++) {
#pragma unroll
        for (int j = 0; j < 4; j++) {
            float lo, hi;
            upk2(acc2[ip][j], lo, hi);
            p[ip * 2 + 0] = fmaf(tanhf(lo + z1bv[j]), z2wv[j], p[ip * 2 + 0]);
            p[ip * 2 + 1] = fmaf(tanhf(hi + z1bv[j]), z2wv[j], p[ip * 2 + 1]);
        }
    }
#pragma unroll
    for (int i = 0; i < 8; i++) {
#pragma unroll
        for (int o = 8; o > 0; o >>= 1)
            p[i] += __shfl_xor_sync(0xffffffffu, p[i], o);
    }
    if (tx == 0) {
#pragma unroll
        for (int i = 0; i < 8; i++)
            g_part[blockIdx.y][b * SS + s0 + ty * 8 + i] = p[i];
    }
}

// ---------------- softmax over S per batch ------------------------------------
__global__ void softmax_kernel()
{
    int b = blockIdx.x, s = threadIdx.x;   // 256 threads
    float l = 0.f;
#pragma unroll
    for (int jb = 0; jb < 8; jb++) l += g_part[jb][b * SS + s];
    __shared__ float sm[256];
    sm[s] = l;
    __syncthreads();
#pragma unroll
    for (int o = 128; o > 0; o >>= 1) {
        if (s < o) sm[s] = fmaxf(sm[s], sm[s + o]);
        __syncthreads();
    }
    float mx = sm[0];
    __syncthreads();
    float e = expf(l - mx);
    sm[s] = e;
    __syncthreads();
#pragma unroll
    for (int o = 128; o > 0; o >>= 1) {
        if (s < o) sm[s] += sm[s + o];
        __syncthreads();
    }
    g_Gt[s * BB + b] = e / sm[0];
}

// ---------------- persistent scan: all 256 steps in one kernel ----------------
// 128 blocks x 256 threads, 1 block/SM. Block owns 4 h-columns; weights for
// those columns live in smem (f32x2 dup-pairs) for the whole kernel.
// Thread (kq = tid>>7, b = tid&127): half the k-range, all 4 h, one b.
__global__ void __launch_bounds__(256, 1) scan_persist(
    const float* __restrict__ facts,
    const float* __restrict__ Ur, const float* __restrict__ U,
    const float* __restrict__ br, const float* __restrict__ bur,
    const float* __restrict__ bw, const float* __restrict__ bu)
{
    __shared__ __align__(16) unsigned long long wpk[HH][4]; // [k][{Ur h01,Ur h23,U h01,U h23}]
    __shared__ unsigned long long red[BB][4];
    __shared__ float hc[5][4];   // rsWr, br+bur, rsW, bw, bu (per local h)

    int tid = threadIdx.x;
    int h0 = blockIdx.x * 4;

    // one-time: pack weight slice into smem
    for (int k = tid; k < HH; k += 256) {
        float4 wr = *reinterpret_cast<const float4*>(Ur + (size_t)k * HH + h0);
        float4 wu = *reinterpret_cast<const float4*>(U  + (size_t)k * HH + h0);
        wpk[k][0] = pk2(wr.x, wr.y);
        wpk[k][1] = pk2(wr.z, wr.w);
        wpk[k][2] = pk2(wu.x, wu.y);
        wpk[k][3] = pk2(wu.z, wu.w);
    }
    if (tid < 4) {
        int h = h0 + tid;
        hc[0][tid] = g_rsWr[h];
        hc[1][tid] = br[h] + bur[h];
        hc[2][tid] = g_rsW[h];
        hc[3][tid] = bw[h];
        hc[4][tid] = bu[h];
    }
    for (int i = tid; i < 4 * BB; i += 256) g_C[0][h0 * BB + i] = 0.f;
    __threadfence();
    grid_sync();

    int kq = tid >> 7;           // 0 / 1 : k-half
    int b  = tid & 127;
    int kbase = kq * 256;

    for (int s = 0; s < SS; s++) {
        const float* __restrict__ Cin = g_C[s & 1];
        float* __restrict__ Cout = g_C[(s + 1) & 1];

        unsigned long long aR01 = 0, aR23 = 0, aU01 = 0, aU23 = 0;
        const float* cp = Cin + (size_t)kbase * BB + b;
#pragma unroll 8
        for (int kk = 0; kk < 256; kk++) {
            float cv = __ldcg(cp + (size_t)kk * BB);          // C written by other SMs
            unsigned long long cd = pk2(cv, cv);
            const unsigned long long* wrow = &wpk[kbase + kk][0];
            ulonglong2 w01 = *reinterpret_cast<const ulonglong2*>(wrow);
            ulonglong2 w23 = *reinterpret_cast<const ulonglong2*>(wrow + 2);
            aR01 = fma2_(cd, w01.x, aR01);
            aR23 = fma2_(cd, w01.y, aR23);
            aU01 = fma2_(cd, w23.x, aU01);
            aU23 = fma2_(cd, w23.y, aU23);
        }
        if (kq == 1) {
            red[b][0] = aR01; red[b][1] = aR23;
            red[b][2] = aU01; red[b][3] = aU23;
        }
        __syncthreads();
        if (kq == 0) {
            aR01 = add2_(aR01, red[b][0]);
            aR23 = add2_(aR23, red[b][1]);
            aU01 = add2_(aU01, red[b][2]);
            aU23 = add2_(aU23, red[b][3]);
            float accR[4], accU[4];
            upk2(aR01, accR[0], accR[1]); upk2(aR23, accR[2], accR[3]);
            upk2(aU01, accU[0], accU[1]); upk2(aU23, accU[2], accU[3]);
            float4 fv4 = *reinterpret_cast<const float4*>(
                facts + ((size_t)b * SS + s) * HH + h0);
            float fa[4] = {fv4.x, fv4.y, fv4.z, fv4.w};
            float g = g_Gt[s * BB + b];
#pragma unroll
            for (int hl = 0; hl < 4; hl++) {
                float c = __ldcg(Cin + (size_t)(h0 + hl) * BB + b);
                float r = 1.f / (1.f + expf(-(fmaf(fa[hl], hc[0][hl], hc[1][hl]) + accR[hl])));
                float preh = fmaf(fa[hl], hc[2][hl], hc[3][hl]);
                float ht = tanhf(fmaf(r, accU[hl] + hc[4][hl], preh));
                Cout[(size_t)(h0 + hl) * BB + b] = fmaf(g, ht - c, c);
            }
        }
        __threadfence();
        grid_sync();
    }
}

// ---------------- final: relu(concat @ nm_w + nm_b) ---------------------------
__global__ void __launch_bounds__(512) final_kernel(
    const float* __restrict__ prevM, const float* __restrict__ q,
    const float* __restrict__ nm_w, const float* __restrict__ nm_b,
    float* __restrict__ out)
{
    __shared__ float cs[3 * HH];
    int b = blockIdx.x, tid = threadIdx.x;    // 512 threads
    cs[tid]          = prevM[b * HH + tid];
    cs[HH + tid]     = g_C[0][(size_t)tid * BB + b];   // final C lives in buffer 0
    cs[2 * HH + tid] = q[b * HH + tid];
    __syncthreads();
    float acc = nm_b[tid];
#pragma unroll 8
    for (int k = 0; k < 3 * HH; k++)
        acc = fmaf(cs[k], nm_w[(size_t)k * HH + tid], acc);
    out[b * HH + tid] = fmaxf(acc, 0.f);
}

// ---------------- launch -------------------------------------------------------
extern "C" void kernel_launch(void* const* d_in, const int* in_sizes, int n_in,
                              void* d_out, int out_size)
{
    const float* facts     = (const float*)d_in[0];
    const float* questions = (const float*)d_in[1];
    const float* prevM     = (const float*)d_in[2];
    const float* z1_w      = (const float*)d_in[3];
    const float* z1_b      = (const float*)d_in[4];
    const float* z2_w      = (const float*)d_in[5];
    // d_in[6] z2_b: constant shift, softmax-invariant — unused
    const float* Wr        = (const float*)d_in[7];
    const float* br        = (const float*)d_in[8];
    const float* Ur        = (const float*)d_in[9];
    const float* bur       = (const float*)d_in[10];
    const float* W         = (const float*)d_in[11];
    const float* bw        = (const float*)d_in[12];
    const float* U         = (const float*)d_in[13];
    const float* bu        = (const float*)d_in[14];
    const float* nm_w      = (const float*)d_in[15];
    const float* nm_b      = (const float*)d_in[16];
    float* out = (float*)d_out;

    prep_kernel<<<128, 256>>>(Wr, W);
    gate_kernel<<<dim3(2, 8, BB), 256>>>(facts, questions, prevM, z1_w, z1_b, z2_w);
    softmax_kernel<<<BB, 256>>>();
    scan_persist<<<NBLK, 256>>>(facts, Ur, U, br, bur, bw, bu);
    final_kernel<<<BB, 512>>>(prevM, questions, nm_w, nm_b, out);
}

// round 5
// speedup vs baseline: 2.5058x; 1.4413x over previous
#include <cuda_runtime.h>
#include <math.h>

#define BB 128
#define SS 256
#define HH 512
#define NBLK 128

// ---------------- device scratch (no allocations allowed) -------------------
__device__ float g_rsWr[HH];            // rowsum(Wr)
__device__ float g_rsW[HH];             // rowsum(W)
__device__ float g_part[4][BB * SS];    // per-jblock logit partials
__device__ float g_Gt[SS * BB];         // softmax gates, (s, b)
__device__ float g_C[2][HH * BB];       // recurrent state, transposed (h, b)
__device__ unsigned g_cnt;              // startup grid barrier counter
__device__ unsigned g_gen;              // startup grid barrier generation
__device__ unsigned g_flags[8];         // per-bg step completion counters

// ---------------- f32x2 helpers ----------------------------------------------
__device__ __forceinline__ unsigned long long pk2(float x, float y) {
    unsigned long long r;
    asm("mov.b64 %0, {%1,%2};" : "=l"(r) : "f"(x), "f"(y));
    return r;
}
__device__ __forceinline__ void upk2(unsigned long long v, float& x, float& y) {
    asm("mov.b64 {%0,%1}, %2;" : "=f"(x), "=f"(y) : "l"(v));
}
__device__ __forceinline__ unsigned long long fma2_(unsigned long long a,
                                                    unsigned long long b,
                                                    unsigned long long c) {
    unsigned long long d;
    asm("fma.rn.f32x2 %0, %1, %2, %3;" : "=l"(d) : "l"(a), "l"(b), "l"(c));
    return d;
}
__device__ __forceinline__ unsigned long long add2_(unsigned long long a,
                                                    unsigned long long b) {
    unsigned long long d;
    asm("add.rn.f32x2 %0, %1, %2;" : "=l"(d) : "l"(a), "l"(b));
    return d;
}
__device__ __forceinline__ float tanh_approx(float x) {
    float y;
    asm("tanh.approx.f32 %0, %1;" : "=f"(y) : "f"(x));
    return y;
}

// ---------------- startup grid barrier (all NBLK blocks co-resident) ---------
__device__ __forceinline__ void grid_sync() {
    __syncthreads();
    if (threadIdx.x == 0) {
        unsigned gen = atomicAdd(&g_gen, 0u);
        unsigned old = atomicAdd(&g_cnt, 1u);
        if (old == NBLK - 1) {
            g_cnt = 0;
            __threadfence();
            atomicAdd(&g_gen, 1u);
        } else {
            while (atomicAdd(&g_gen, 0u) == gen) {}
        }
        __threadfence();
    }
    __syncthreads();
}

// ---------------- prep: rowsums of Wr and W ----------------------------------
__global__ void prep_kernel(const float* __restrict__ Wr, const float* __restrict__ W)
{
    int warp = threadIdx.x >> 5, lane = threadIdx.x & 31;
    int rowId = blockIdx.x * 8 + warp;               // 0..1023
    const float* src = (rowId < HH) ? Wr : W;
    int h = rowId & (HH - 1);
    const float4* s4 = reinterpret_cast<const float4*>(src + (size_t)h * HH);
    float s = 0.f;
    for (int i = lane; i < HH / 4; i += 32) {
        float4 v = s4[i];
        s += (v.x + v.y) + (v.z + v.w);
    }
#pragma unroll
    for (int o = 16; o > 0; o >>= 1) s += __shfl_xor_sync(0xffffffffu, s, o);
    if (lane == 0) {
        if (rowId < HH) g_rsWr[h] = s;
        else            g_rsW[h]  = s;
    }
}

// ---------------- gate MLP: fused z-build + GEMM (f32x2, 8x8) + tanh + dot ---
// grid (S/128, 512/128, B), 256 threads. 128x128 tile, K=2048 built on the fly.
__global__ void __launch_bounds__(256, 2) gate_kernel(
    const float* __restrict__ facts, const float* __restrict__ q,
    const float* __restrict__ m, const float* __restrict__ z1w,
    const float* __restrict__ z1b, const float* __restrict__ z2w)
{
    __shared__ float qs[HH], ms[HH];
    __shared__ float As[4][16][132];   // padded rows: kill 16-way STS conflicts
    __shared__ float Bs[16][128];

    int tid = threadIdx.x;
    int b  = blockIdx.z;
    int s0 = blockIdx.x * 128;
    int j0 = blockIdx.y * 128;

    for (int i = tid; i < HH; i += 256) {
        qs[i] = q[b * HH + i];
        ms[i] = m[b * HH + i];
    }

    int tx = tid & 15, ty = tid >> 4;     // tx: 8 j's, ty: 8 s's
    unsigned long long acc2[4][8];        // [s-pair][j]
#pragma unroll
    for (int i = 0; i < 4; i++)
#pragma unroll
        for (int j = 0; j < 8; j++) acc2[i][j] = 0ull;

    const float* fb = facts + ((size_t)b * SS + s0) * HH;

    for (int k0 = 0; k0 < HH; k0 += 16) {
        __syncthreads();   // prev compute done (also covers qs/ms on k0==0)
        for (int i = tid; i < 128 * 16; i += 256) {
            int ss = i >> 4, kk = i & 15;
            float fv = fb[(size_t)ss * HH + k0 + kk];
            float qv = qs[k0 + kk], mv = ms[k0 + kk];
            As[0][kk][ss] = fv * qv;
            As[1][kk][ss] = fv * mv;
            As[2][kk][ss] = fabsf(fv - qv);
            As[3][kk][ss] = fabsf(fv - mv);
        }
        for (int blk = 0; blk < 4; blk++) {
            __syncthreads();   // As ready / prev Bs consumed
            for (int i = tid; i < 16 * 128; i += 256) {
                int kk = i >> 7, jj = i & 127;
                Bs[kk][jj] = z1w[(size_t)(blk * HH + k0 + kk) * HH + j0 + jj];
            }
            __syncthreads();   // Bs ready
#pragma unroll
            for (int kk = 0; kk < 16; kk++) {
                ulonglong2 a01 = *reinterpret_cast<const ulonglong2*>(&As[blk][kk][ty * 8]);
                ulonglong2 a23 = *reinterpret_cast<const ulonglong2*>(&As[blk][kk][ty * 8 + 4]);
                float4 bv0 = *reinterpret_cast<const float4*>(&Bs[kk][tx * 8]);
                float4 bv1 = *reinterpret_cast<const float4*>(&Bs[kk][tx * 8 + 4]);
                unsigned long long ap[4] = {a01.x, a01.y, a23.x, a23.y};
                float bf[8] = {bv0.x, bv0.y, bv0.z, bv0.w, bv1.x, bv1.y, bv1.z, bv1.w};
#pragma unroll
                for (int j = 0; j < 8; j++) {
                    unsigned long long bd = pk2(bf[j], bf[j]);
#pragma unroll
                    for (int i = 0; i < 4; i++)
                        acc2[i][j] = fma2_(ap[i], bd, acc2[i][j]);
                }
            }
        }
    }

    // epilogue: tanh (approx), dot with z2_w, reduce over the 128 j's
    float z1bv[8], z2wv[8];
#pragma unroll
    for (int j = 0; j < 8; j++) {
        int jc = j0 + tx * 8 + j;
        z1bv[j] = z1b[jc];
        z2wv[j] = z2w[jc];
    }
    float p[8];
#pragma unroll
    for (int i = 0; i < 8; i++) p[i] = 0.f;
#pragma unroll
    for (int ip = 0; ip < 4; ip++) {
#pragma unroll
        for (int j = 0; j < 8; j++) {
            float lo, hi;
            upk2(acc2[ip][j], lo, hi);
            p[ip * 2 + 0] = fmaf(tanh_approx(lo + z1bv[j]), z2wv[j], p[ip * 2 + 0]);
            p[ip * 2 + 1] = fmaf(tanh_approx(hi + z1bv[j]), z2wv[j], p[ip * 2 + 1]);
        }
    }
#pragma unroll
    for (int i = 0; i < 8; i++) {
#pragma unroll
        for (int o = 8; o > 0; o >>= 1)
            p[i] += __shfl_xor_sync(0xffffffffu, p[i], o);
    }
    if (tx == 0) {
#pragma unroll
        for (int i = 0; i < 8; i++)
            g_part[blockIdx.y][b * SS + s0 + ty * 8 + i] = p[i];
    }
}

// ---------------- softmax over S per batch ------------------------------------
__global__ void softmax_kernel()
{
    int b = blockIdx.x, s = threadIdx.x;   // 256 threads
    float l = 0.f;
#pragma unroll
    for (int jb = 0; jb < 4; jb++) l += g_part[jb][b * SS + s];
    __shared__ float sm[256];
    sm[s] = l;
    __syncthreads();
#pragma unroll
    for (int o = 128; o > 0; o >>= 1) {
        if (s < o) sm[s] = fmaxf(sm[s], sm[s + o]);
        __syncthreads();
    }
    float mx = sm[0];
    __syncthreads();
    float e = expf(l - mx);
    sm[s] = e;
    __syncthreads();
#pragma unroll
    for (int o = 128; o > 0; o >>= 1) {
        if (s < o) sm[s] += sm[s + o];
        __syncthreads();
    }
    g_Gt[s * BB + b] = e / sm[0];
}

// ---------------- persistent scan: 128 blocks = 16 hgroups x 8 bgroups --------
// Block owns 32 h x 16 b. Weights (128KB, f32x2 h-pairs) live in dynamic smem
// for the whole kernel; per step the 32KB C-slice is staged (duplicated) into
// smem. Per-bg completion flags replace the global lock-step barrier.
__global__ void __launch_bounds__(512, 1) scan_persist(
    const float* __restrict__ facts,
    const float* __restrict__ Ur, const float* __restrict__ U,
    const float* __restrict__ br, const float* __restrict__ bur,
    const float* __restrict__ bw, const float* __restrict__ bu)
{
    extern __shared__ __align__(16) char dsm[];
    unsigned long long* wpk = reinterpret_cast<unsigned long long*>(dsm);           // [512][32]
    unsigned long long* Cs2 = reinterpret_cast<unsigned long long*>(dsm + 131072);  // [512][16]
    unsigned long long* red = Cs2;                                                  // alias [8][64][8]

    __shared__ unsigned long long fin[32][16];
    __shared__ float hcs[5][32];

    int tid = threadIdx.x;
    int hg = blockIdx.x >> 3;      // 0..15
    int bg = blockIdx.x & 7;       // 0..7
    int h0 = hg * 32;
    int b0 = bg * 16;

    // one-time: pack weight slice (h-pairs for Ur at j<16, U at j>=16)
    for (int i = tid; i < 512 * 8; i += 512) {
        int k = i >> 3, qd = i & 7;
        float4 r4 = *reinterpret_cast<const float4*>(Ur + (size_t)k * HH + h0 + qd * 4);
        float4 u4 = *reinterpret_cast<const float4*>(U  + (size_t)k * HH + h0 + qd * 4);
        wpk[k * 32 + qd * 2]          = pk2(r4.x, r4.y);
        wpk[k * 32 + qd * 2 + 1]      = pk2(r4.z, r4.w);
        wpk[k * 32 + 16 + qd * 2]     = pk2(u4.x, u4.y);
        wpk[k * 32 + 16 + qd * 2 + 1] = pk2(u4.z, u4.w);
    }
    if (tid < 32) {
        int h = h0 + tid;
        hcs[0][tid] = g_rsWr[h];
        hcs[1][tid] = br[h] + bur[h];
        hcs[2][tid] = g_rsW[h];
        hcs[3][tid] = bw[h];
        hcs[4][tid] = bu[h];
    }
    // zero own C0 chunk; reset flags
    for (int i = tid; i < 32 * 16; i += 512) {
        int hl = i >> 4, bl = i & 15;
        g_C[0][(size_t)(h0 + hl) * BB + b0 + bl] = 0.f;
    }
    if (hg == 0 && tid == 0) g_flags[bg] = 0u;
    __threadfence();
    grid_sync();

    // compute mapping: thread = ks(8) x jq(8) x bp(8); warp = 4 jq x 8 bp
    int ks = tid >> 6;
    int jq = (tid >> 3) & 7;
    int bp = tid & 7;
    int slot = jq * 8 + bp;

    // epilogue mapping: thread = b(16) x h_local(32); warp spans h (coalesced facts)
    int eb  = tid >> 5;
    int ehl = tid & 31;
    float cur_c = 0.f;

    volatile unsigned* flagp = &g_flags[bg];

    for (int s = 0; s < SS; s++) {
        const float* __restrict__ Cin = g_C[s & 1];
        float* __restrict__ Cout = g_C[(s + 1) & 1];

        if (s > 0) {
            if (tid == 0) {
                unsigned target = 16u * (unsigned)s;
                while (*flagp < target) {}
                __threadfence();
            }
            __syncthreads();
        }

        // stage C slice, duplicated for f32x2
        for (int i = tid; i < 512 * 16; i += 512) {
            int k = i >> 4, bl = i & 15;
            float c = __ldcg(Cin + (size_t)k * BB + b0 + bl);
            Cs2[k * 16 + bl] = pk2(c, c);
        }
        __syncthreads();

        unsigned long long acc[2][4];
#pragma unroll
        for (int i = 0; i < 2; i++)
#pragma unroll
            for (int j = 0; j < 4; j++) acc[i][j] = 0ull;

        int kb = ks * 64;
#pragma unroll 4
        for (int kk = 0; kk < 64; kk++) {
            int k = kb + kk;
            ulonglong2 cd = *reinterpret_cast<const ulonglong2*>(&Cs2[k * 16 + bp * 2]);
            ulonglong2 w0 = *reinterpret_cast<const ulonglong2*>(&wpk[k * 32 + jq * 4]);
            ulonglong2 w1 = *reinterpret_cast<const ulonglong2*>(&wpk[k * 32 + jq * 4 + 2]);
            acc[0][0] = fma2_(cd.x, w0.x, acc[0][0]);
            acc[0][1] = fma2_(cd.x, w0.y, acc[0][1]);
            acc[0][2] = fma2_(cd.x, w1.x, acc[0][2]);
            acc[0][3] = fma2_(cd.x, w1.y, acc[0][3]);
            acc[1][0] = fma2_(cd.y, w0.x, acc[1][0]);
            acc[1][1] = fma2_(cd.y, w0.y, acc[1][1]);
            acc[1][2] = fma2_(cd.y, w1.x, acc[1][2]);
            acc[1][3] = fma2_(cd.y, w1.y, acc[1][3]);
        }
        __syncthreads();   // Cs2 reads done before alias (red) writes

        unsigned long long* rp = &red[((size_t)ks * 64 + slot) * 8];
#pragma unroll
        for (int i = 0; i < 2; i++)
#pragma unroll
            for (int j = 0; j < 4; j++) rp[i * 4 + j] = acc[i][j];
        __syncthreads();

        // sum the 8 k-split partials -> fin[j][b]
        {
            int sl = tid >> 3, u = tid & 7;
            unsigned long long v = red[(size_t)sl * 8 + u];
#pragma unroll
            for (int k2 = 1; k2 < 8; k2++)
                v = add2_(v, red[((size_t)k2 * 64 + sl) * 8 + u]);
            int bi = u >> 2, ji = u & 3;
            int jq2 = sl >> 3, bp2 = sl & 7;
            fin[jq2 * 4 + ji][bp2 * 2 + bi] = v;
        }
        __syncthreads();

        // epilogue: nonlinearity + blend; keep own C in a register
        {
            int jp = ehl >> 1, half = ehl & 1;
            float r0, r1, u0, u1;
            upk2(fin[jp][eb], r0, r1);
            upk2(fin[16 + jp][eb], u0, u1);
            float aR = half ? r1 : r0;
            float aU = half ? u1 : u0;
            int h = h0 + ehl, bglob = b0 + eb;
            float fv = __ldg(facts + ((size_t)bglob * SS + s) * HH + h);
            float g = g_Gt[s * BB + bglob];
            float rr = 1.f / (1.f + expf(-(fmaf(fv, hcs[0][ehl], hcs[1][ehl]) + aR)));
            float ht = tanhf(fmaf(rr, aU + hcs[4][ehl], fmaf(fv, hcs[2][ehl], hcs[3][ehl])));
            cur_c = fmaf(g, ht - cur_c, cur_c);
            Cout[(size_t)h * BB + bglob] = cur_c;
        }
        __syncthreads();
        if (tid == 0) {
            __threadfence();
            atomicAdd((unsigned*)&g_flags[bg], 1u);
        }
    }
}

// ---------------- final: relu(concat @ nm_w + nm_b) ---------------------------
__global__ void __launch_bounds__(512) final_kernel(
    const float* __restrict__ prevM, const float* __restrict__ q,
    const float* __restrict__ nm_w, const float* __restrict__ nm_b,
    float* __restrict__ out)
{
    __shared__ float cs[3 * HH];
    int b = blockIdx.x, tid = threadIdx.x;    // 512 threads
    cs[tid]          = prevM[b * HH + tid];
    cs[HH + tid]     = g_C[0][(size_t)tid * BB + b];   // final C lives in buffer 0
    cs[2 * HH + tid] = q[b * HH + tid];
    __syncthreads();
    float acc = nm_b[tid];
#pragma unroll 8
    for (int k = 0; k < 3 * HH; k++)
        acc = fmaf(cs[k], nm_w[(size_t)k * HH + tid], acc);
    out[b * HH + tid] = fmaxf(acc, 0.f);
}

// ---------------- launch -------------------------------------------------------
extern "C" void kernel_launch(void* const* d_in, const int* in_sizes, int n_in,
                              void* d_out, int out_size)
{
    const float* facts     = (const float*)d_in[0];
    const float* questions = (const float*)d_in[1];
    const float* prevM     = (const float*)d_in[2];
    const float* z1_w      = (const float*)d_in[3];
    const float* z1_b      = (const float*)d_in[4];
    const float* z2_w      = (const float*)d_in[5];
    // d_in[6] z2_b: constant shift, softmax-invariant — unused
    const float* Wr        = (const float*)d_in[7];
    const float* br        = (const float*)d_in[8];
    const float* Ur        = (const float*)d_in[9];
    const float* bur       = (const float*)d_in[10];
    const float* W         = (const float*)d_in[11];
    const float* bw        = (const float*)d_in[12];
    const float* U         = (const float*)d_in[13];
    const float* bu        = (const float*)d_in[14];
    const float* nm_w      = (const float*)d_in[15];
    const float* nm_b      = (const float*)d_in[16];
    float* out = (float*)d_out;

    const int scan_smem = 131072 + 65536;   // wpk + Cs2/red = 192KB
    cudaFuncSetAttribute(scan_persist,
                         cudaFuncAttributeMaxDynamicSharedMemorySize, scan_smem);

    prep_kernel<<<128, 256>>>(Wr, W);
    gate_kernel<<<dim3(2, 4, BB), 256>>>(facts, questions, prevM, z1_w, z1_b, z2_w);
    softmax_kernel<<<BB, 256>>>();
    scan_persist<<<NBLK, 512, scan_smem>>>(facts, Ur, U, br, bur, bw, bu);
    final_kernel<<<BB, 512>>>(prevM, questions, nm_w, nm_b, out);
}